// round 4
// baseline (speedup 1.0000x reference)
#include <cuda_runtime.h>
#include <math.h>
#include <stdint.h>

// Problem constants
#define T_   2048
#define E_   16
#define H_   2048
#define I_   1408
#define K_   4
#define A_TOT (T_ * K_)   // 8192 assignments

// GEMM tiling (tf32 mma.sync), CTA 256x128, warp 64x64
#define BM 256
#define BN 128
#define BK 32
#define STAGES 3
#define AFLT (BM * BK)            // 8192 floats
#define BFLT (BN * BK)            // 4096 floats
#define SFLT (AFLT + BFLT)        // 12288 floats per stage
#define GEMM_SMEM (STAGES * SFLT * 4)   // 147456 bytes

// ---------------- Device scratch ----------------
__device__ int   d_topk_idx[A_TOT];
__device__ float d_topk_w[A_TOT];
__device__ int   d_tok[A_TOT];
__device__ float d_wt[A_TOT];
__device__ int   d_pos[A_TOT];
__device__ int   d_off[E_ + 1];
__device__ float d_xs[(size_t)A_TOT * H_];    // gathered + tf32-rounded x
__device__ float d_g[(size_t)A_TOT * I_];     // gate raw
__device__ float d_hbuf[(size_t)A_TOT * I_];  // silu(g)*u, tf32-rounded
__device__ float d_obuf[(size_t)A_TOT * H_];  // weighted down outputs

// ---------------- helpers ----------------
__device__ __forceinline__ uint32_t smem_u32(const void* p) {
    uint32_t a;
    asm("{ .reg .u64 t; cvta.to.shared.u64 t, %1; cvt.u32.u64 %0, t; }" : "=r"(a) : "l"(p));
    return a;
}
__device__ __forceinline__ float rna_tf32(float v) {
    uint32_t r;
    asm("cvt.rna.tf32.f32 %0, %1;" : "=r"(r) : "f"(v));
    return __uint_as_float(r);
}
__device__ __forceinline__ uint32_t rna_tf32_u(float v) {
    uint32_t r;
    asm("cvt.rna.tf32.f32 %0, %1;" : "=r"(r) : "f"(v));
    return r;
}

#define MMA_TF32(c, a, b) \
    asm volatile("mma.sync.aligned.m16n8k8.row.col.f32.tf32.tf32.f32 " \
        "{%0,%1,%2,%3}, {%4,%5,%6,%7}, {%8,%9}, {%0,%1,%2,%3};" \
        : "+f"((c)[0]), "+f"((c)[1]), "+f"((c)[2]), "+f"((c)[3]) \
        : "r"((a)[0]), "r"((a)[1]), "r"((a)[2]), "r"((a)[3]), "r"((b)[0]), "r"((b)[1]))

// ---------------- 1. Router ----------------
__global__ void router_kernel(const float* __restrict__ logits) {
    int t = blockIdx.x * blockDim.x + threadIdx.x;
    if (t >= T_) return;
    float l[E_];
#pragma unroll
    for (int e = 0; e < E_; e++) l[e] = logits[t * E_ + e];
    unsigned used = 0u;
    float val[K_]; int idx[K_];
#pragma unroll
    for (int k = 0; k < K_; k++) {
        float bv = -INFINITY; int bi = 0;
#pragma unroll
        for (int e = 0; e < E_; e++) {
            bool ok = !((used >> e) & 1u) && (l[e] > bv);
            bv = ok ? l[e] : bv;
            bi = ok ? e : bi;
        }
        used |= (1u << bi);
        val[k] = bv; idx[k] = bi;
    }
    float m = val[0], s = 0.f;
#pragma unroll
    for (int k = 0; k < K_; k++) { val[k] = __expf(val[k] - m); s += val[k]; }
    float inv = 1.f / s;
#pragma unroll
    for (int k = 0; k < K_; k++) {
        d_topk_idx[t * K_ + k] = idx[k];
        d_topk_w[t * K_ + k]   = val[k] * inv;
    }
}

// ---------------- 2. Deterministic counting sort ----------------
__global__ void sort_kernel() {
    __shared__ int sidx[A_TOT];
    __shared__ int scnt[256];
    __shared__ int sbase[256];
    int tid = threadIdx.x;
    for (int a = tid; a < A_TOT; a += 256) sidx[a] = d_topk_idx[a];
    __syncthreads();
    const int CH = A_TOT / 16;
    int e = tid >> 4, c = tid & 15, cn = 0;
    for (int a = c * CH; a < (c + 1) * CH; a++) cn += (sidx[a] == e);
    scnt[tid] = cn;
    __syncthreads();
    if (tid == 0) {
        int run = 0;
        for (int ee = 0; ee < E_; ee++) {
            d_off[ee] = run;
            for (int cc = 0; cc < 16; cc++) { sbase[ee * 16 + cc] = run; run += scnt[ee * 16 + cc]; }
        }
        d_off[E_] = run;
    }
    __syncthreads();
    int p = sbase[tid];
    for (int a = c * CH; a < (c + 1) * CH; a++) {
        if (sidx[a] == e) {
            d_tok[p] = a >> 2;
            d_wt[p]  = d_topk_w[a];
            d_pos[a] = p;
            p++;
        }
    }
}

// ---------------- 3. Gather x rows (tf32 rounding) ----------------
__global__ void gather_kernel(const float* __restrict__ x) {
    int p = blockIdx.x;
    int tok = d_tok[p];
    const float4* src = (const float4*)(x + (size_t)tok * H_);
    float4* dst = (float4*)(d_xs + (size_t)p * H_);
    for (int i = threadIdx.x; i < H_ / 4; i += 256) {
        float4 v = src[i];
        v.x = rna_tf32(v.x); v.y = rna_tf32(v.y);
        v.z = rna_tf32(v.z); v.w = rna_tf32(v.w);
        dst[i] = v;
    }
}

// ---------------- 4. Grouped GEMM (tf32 mma.sync) ----------------
// mode 0: C = A*B^T                     (gate)
// mode 1: C = rna(silu(G)*A*B^T)        (up, fused SiLU with d_g)
// mode 2: C = wt[m] * A*B^T             (down)
#define ISSUE_STAGE(kt, st) do {                                                  \
    if ((kt) < NT) {                                                              \
        int k0 = (kt) * BK;                                                       \
        uint32_t sa = smbase + (st) * (SFLT * 4);                                 \
        uint32_t sbb = sa + AFLT * 4;                                             \
        _Pragma("unroll")                                                         \
        for (int i = 0; i < 8; i++) {                                             \
            int r = lr + 32 * i;                                                  \
            uint32_t sw = (uint32_t)((r * 32 + ((lj ^ (r & 7)) << 2)) * 4);       \
            int ra = base + m0 + r; if (ra > A_TOT - 1) ra = A_TOT - 1;           \
            const float* srca = A + (size_t)ra * Kdim + k0 + lj * 4;              \
            int vs = (m0 + r < n_e) ? 16 : 0;                                     \
            asm volatile("cp.async.cg.shared.global [%0], [%1], 16, %2;"          \
                         :: "r"(sa + sw), "l"(srca), "r"(vs) : "memory");         \
        }                                                                         \
        _Pragma("unroll")                                                         \
        for (int i = 0; i < 4; i++) {                                             \
            int r = lr + 32 * i;                                                  \
            uint32_t sw = (uint32_t)((r * 32 + ((lj ^ (r & 7)) << 2)) * 4);       \
            const float* srcb = Bexp + (size_t)(n0 + r) * Kdim + k0 + lj * 4;     \
            asm volatile("cp.async.cg.shared.global [%0], [%1], 16;"              \
                         :: "r"(sbb + sw), "l"(srcb) : "memory");                 \
        }                                                                         \
    }                                                                             \
    asm volatile("cp.async.commit_group;" ::: "memory");                          \
} while (0)

__global__ __launch_bounds__(256)
void gemm_tc(const float* __restrict__ A, const float* __restrict__ Bw,
             float* __restrict__ C, const float* __restrict__ G,
             int Kdim, int N, int mode) {
    int e = blockIdx.z;
    int base = d_off[e];
    int n_e  = d_off[e + 1] - base;
    int m0 = blockIdx.y * BM;
    if (m0 >= n_e) return;
    int n0 = blockIdx.x * BN;

    extern __shared__ float sm[];
    uint32_t smbase = smem_u32(sm);
    int tid = threadIdx.x;
    int wid = tid >> 5, lane = tid & 31;
    int q = lane >> 2, tig = lane & 3;
    int lr = tid >> 3, lj = tid & 7;          // cp.async: row-of-32, 16B chunk

    const float* Bexp = Bw + (size_t)e * N * Kdim;
    int NT = Kdim / BK;

    ISSUE_STAGE(0, 0);
    ISSUE_STAGE(1, 1);

    int wm = (wid & 3) << 6;    // warp M band: 0/64/128/192
    int wn = (wid >> 2) << 6;   // warp N band: 0/64

    float acc[4][8][4];
#pragma unroll
    for (int mt = 0; mt < 4; mt++)
#pragma unroll
        for (int nt = 0; nt < 8; nt++)
#pragma unroll
            for (int r = 0; r < 4; r++) acc[mt][nt][r] = 0.f;

    int rowAoff[4], rowBoff[8];
#pragma unroll
    for (int mt = 0; mt < 4; mt++) rowAoff[mt] = (wm + mt * 16 + q) * 32 + tig;
#pragma unroll
    for (int nt = 0; nt < 8; nt++) rowBoff[nt] = (wn + nt * 8 + q) * 32 + tig;

    for (int kt = 0; kt < NT; kt++) {
        asm volatile("cp.async.wait_group 1;" ::: "memory");
        __syncthreads();
        ISSUE_STAGE(kt + 2, (kt + 2) % STAGES);
        const float* As = sm + (kt % STAGES) * SFLT;
        const float* Bs = As + AFLT;
#pragma unroll
        for (int kk = 0; kk < 4; kk++) {
            int x0 = ((2 * kk) ^ q) << 2;
            uint32_t a[4][4];
#pragma unroll
            for (int mt = 0; mt < 4; mt++) {
                a[mt][0] = __float_as_uint(As[rowAoff[mt] + x0]);
                a[mt][1] = __float_as_uint(As[rowAoff[mt] + 256 + x0]);
                a[mt][2] = __float_as_uint(As[rowAoff[mt] + (x0 ^ 4)]);
                a[mt][3] = __float_as_uint(As[rowAoff[mt] + 256 + (x0 ^ 4)]);
            }
            uint32_t b[8][2];
#pragma unroll
            for (int nt = 0; nt < 8; nt++) {
                b[nt][0] = rna_tf32_u(Bs[rowBoff[nt] + x0]);
                b[nt][1] = rna_tf32_u(Bs[rowBoff[nt] + (x0 ^ 4)]);
            }
#pragma unroll
            for (int mt = 0; mt < 4; mt++)
#pragma unroll
                for (int nt = 0; nt < 8; nt++)
                    MMA_TF32(acc[mt][nt], a[mt], b[nt]);
        }
    }

    // epilogue
#pragma unroll
    for (int mt = 0; mt < 4; mt++) {
        int m  = m0 + wm + mt * 16 + q;
        int m8 = m + 8;
        float w0 = 1.f, w1 = 1.f;
        if (mode == 2) {
            w0 = (m  < n_e) ? d_wt[base + m]  : 0.f;
            w1 = (m8 < n_e) ? d_wt[base + m8] : 0.f;
        }
#pragma unroll
        for (int nt = 0; nt < 8; nt++) {
            int n = n0 + wn + nt * 8 + 2 * tig;
            if (m < n_e) {
                size_t o = (size_t)(base + m) * N + n;
                float2 v = make_float2(acc[mt][nt][0], acc[mt][nt][1]);
                if (mode == 1) {
                    float2 g = *(const float2*)&G[o];
                    v.x = rna_tf32(g.x * (1.f / (1.f + __expf(-g.x))) * v.x);
                    v.y = rna_tf32(g.y * (1.f / (1.f + __expf(-g.y))) * v.y);
                } else { v.x *= w0; v.y *= w0; }
                *(float2*)&C[o] = v;
            }
            if (m8 < n_e) {
                size_t o = (size_t)(base + m8) * N + n;
                float2 v = make_float2(acc[mt][nt][2], acc[mt][nt][3]);
                if (mode == 1) {
                    float2 g = *(const float2*)&G[o];
                    v.x = rna_tf32(g.x * (1.f / (1.f + __expf(-g.x))) * v.x);
                    v.y = rna_tf32(g.y * (1.f / (1.f + __expf(-g.y))) * v.y);
                } else { v.x *= w1; v.y *= w1; }
                *(float2*)&C[o] = v;
            }
        }
    }
}

// ---------------- 5. Combine ----------------
__global__ void combine_kernel(float* __restrict__ out) {
    int gid = blockIdx.x * blockDim.x + threadIdx.x;
    int t = gid / (H_ / 4);
    int h4 = (gid - t * (H_ / 4)) * 4;
    float4 s = make_float4(0.f, 0.f, 0.f, 0.f);
#pragma unroll
    for (int k = 0; k < K_; k++) {
        int p = d_pos[t * K_ + k];
        float4 v = *(const float4*)&d_obuf[(size_t)p * H_ + h4];
        s.x += v.x; s.y += v.y; s.z += v.z; s.w += v.w;
    }
    *(float4*)&out[(size_t)t * H_ + h4] = s;
}

// ---------------- Host ----------------
extern "C" void kernel_launch(void* const* d_in, const int* in_sizes, int n_in,
                              void* d_out, int out_size) {
    const float* x      = (const float*)d_in[0];
    const float* logits = (const float*)d_in[1];
    const float* gate_w = (const float*)d_in[2];
    const float* up_w   = (const float*)d_in[3];
    const float* down_w = (const float*)d_in[4];
    float* out = (float*)d_out;

    static int smem_set = 0;
    if (!smem_set) {
        cudaFuncSetAttribute(gemm_tc, cudaFuncAttributeMaxDynamicSharedMemorySize, GEMM_SMEM);
        smem_set = 1;
    }

    float *xs_p, *g_p, *h_p, *o_p;
    cudaGetSymbolAddress((void**)&xs_p, d_xs);
    cudaGetSymbolAddress((void**)&g_p,  d_g);
    cudaGetSymbolAddress((void**)&h_p,  d_hbuf);
    cudaGetSymbolAddress((void**)&o_p,  d_obuf);

    router_kernel<<<T_ / 256, 256>>>(logits);
    sort_kernel<<<1, 256>>>();
    gather_kernel<<<A_TOT, 256>>>(x);

    dim3 g1(I_ / BN, T_ / BM, E_);   // 11 x 8 x 16
    gemm_tc<<<g1, 256, GEMM_SMEM>>>(xs_p, gate_w, g_p, nullptr, H_, I_, 0);
    gemm_tc<<<g1, 256, GEMM_SMEM>>>(xs_p, up_w,   h_p, g_p,     H_, I_, 1);

    dim3 g2(H_ / BN, T_ / BM, E_);   // 16 x 8 x 16
    gemm_tc<<<g2, 256, GEMM_SMEM>>>(h_p, down_w, o_p, nullptr, I_, H_, 2);

    combine_kernel<<<(T_ * H_ / 4) / 256, 256>>>(out);
}

// round 6
// speedup vs baseline: 1.5026x; 1.5026x over previous
#include <cuda_runtime.h>
#include <cuda_fp16.h>
#include <math.h>
#include <stdint.h>

// Problem constants
#define T_   2048
#define E_   16
#define H_   2048
#define I_   1408
#define K_   4
#define A_TOT (T_ * K_)   // 8192 assignments
#define WELEM ((size_t)E_ * I_ * H_)   // 46,137,344 (same for all 3 weights)

// GEMM tiling (fp16 mma.sync m16n8k16), CTA 256x128, warp 64x64
#define BM 256
#define BN 128
#define BK 64                         // halves per k-tile (128 bytes per row)
#define STAGES 3
#define A_BYTES (BM * 128)            // 32768
#define B_BYTES (BN * 128)            // 16384
#define STAGE_BYTES (A_BYTES + B_BYTES)      // 49152
#define GEMM_SMEM (STAGES * STAGE_BYTES)     // 147456

// ---------------- Device scratch ----------------
__device__ int    d_topk_idx[A_TOT];
__device__ float  d_topk_w[A_TOT];
__device__ int    d_tok[A_TOT];
__device__ float  d_wt[A_TOT];
__device__ int    d_pos[A_TOT];
__device__ int    d_off[E_ + 1];
__device__ __half d_xs16[(size_t)A_TOT * H_];   // gathered x, fp16
__device__ __half d_gw16[WELEM];                // gate_w fp16
__device__ __half d_uw16[WELEM];                // up_w fp16
__device__ __half d_dw16[WELEM];                // down_w fp16
__device__ float  d_g[(size_t)A_TOT * I_];      // gate output fp32
__device__ __half d_h16[(size_t)A_TOT * I_];    // silu(g)*u fp16
__device__ float  d_obuf[(size_t)A_TOT * H_];   // weighted down outputs fp32

// ---------------- helpers ----------------
__device__ __forceinline__ uint32_t smem_u32(const void* p) {
    uint32_t a;
    asm("{ .reg .u64 t; cvta.to.shared.u64 t, %1; cvt.u32.u64 %0, t; }" : "=r"(a) : "l"(p));
    return a;
}
__device__ __forceinline__ uint32_t h2_u32(__half2 h) {
    __half2_raw r = *(__half2_raw*)&h;
    return (uint32_t)r.x | ((uint32_t)r.y << 16);
}
__device__ __forceinline__ uint32_t pack_f2h(float a, float b) {
    uint32_t r;
    asm("{ .reg .f16 lo, hi;\n\t"
        "cvt.rn.f16.f32 lo, %1;\n\t"
        "cvt.rn.f16.f32 hi, %2;\n\t"
        "mov.b32 %0, {lo, hi}; }"
        : "=r"(r) : "f"(a), "f"(b));
    return r;
}

#define MMA_F16(c, a, b) \
    asm volatile("mma.sync.aligned.m16n8k16.row.col.f32.f16.f16.f32 " \
        "{%0,%1,%2,%3}, {%4,%5,%6,%7}, {%8,%9}, {%0,%1,%2,%3};" \
        : "+f"((c)[0]), "+f"((c)[1]), "+f"((c)[2]), "+f"((c)[3]) \
        : "r"((a)[0]), "r"((a)[1]), "r"((a)[2]), "r"((a)[3]), "r"((b)[0]), "r"((b)[1]))

// ---------------- 0. Weight convert fp32 -> fp16 ----------------
__global__ void convert_kernel(const float4* __restrict__ src, uint4* __restrict__ dst,
                               size_t n8) {
    size_t i = (size_t)blockIdx.x * blockDim.x + threadIdx.x;
    if (i >= n8) return;
    float4 v0 = src[2 * i];
    float4 v1 = src[2 * i + 1];
    uint4 o;
    o.x = pack_f2h(v0.x, v0.y);
    o.y = pack_f2h(v0.z, v0.w);
    o.z = pack_f2h(v1.x, v1.y);
    o.w = pack_f2h(v1.z, v1.w);
    dst[i] = o;
}

// ---------------- 1. Router ----------------
__global__ void router_kernel(const float* __restrict__ logits) {
    int t = blockIdx.x * blockDim.x + threadIdx.x;
    if (t >= T_) return;
    float l[E_];
#pragma unroll
    for (int e = 0; e < E_; e++) l[e] = logits[t * E_ + e];
    unsigned used = 0u;
    float val[K_]; int idx[K_];
#pragma unroll
    for (int k = 0; k < K_; k++) {
        float bv = -INFINITY; int bi = 0;
#pragma unroll
        for (int e = 0; e < E_; e++) {
            bool ok = !((used >> e) & 1u) && (l[e] > bv);
            bv = ok ? l[e] : bv;
            bi = ok ? e : bi;
        }
        used |= (1u << bi);
        val[k] = bv; idx[k] = bi;
    }
    float m = val[0], s = 0.f;
#pragma unroll
    for (int k = 0; k < K_; k++) { val[k] = __expf(val[k] - m); s += val[k]; }
    float inv = 1.f / s;
#pragma unroll
    for (int k = 0; k < K_; k++) {
        d_topk_idx[t * K_ + k] = idx[k];
        d_topk_w[t * K_ + k]   = val[k] * inv;
    }
}

// ---------------- 2. Deterministic counting sort ----------------
__global__ void sort_kernel() {
    __shared__ int sidx[A_TOT];
    __shared__ int scnt[256];
    __shared__ int sbase[256];
    int tid = threadIdx.x;
    for (int a = tid; a < A_TOT; a += 256) sidx[a] = d_topk_idx[a];
    __syncthreads();
    const int CH = A_TOT / 16;
    int e = tid >> 4, c = tid & 15, cn = 0;
    for (int a = c * CH; a < (c + 1) * CH; a++) cn += (sidx[a] == e);
    scnt[tid] = cn;
    __syncthreads();
    if (tid == 0) {
        int run = 0;
        for (int ee = 0; ee < E_; ee++) {
            d_off[ee] = run;
            for (int cc = 0; cc < 16; cc++) { sbase[ee * 16 + cc] = run; run += scnt[ee * 16 + cc]; }
        }
        d_off[E_] = run;
    }
    __syncthreads();
    int p = sbase[tid];
    for (int a = c * CH; a < (c + 1) * CH; a++) {
        if (sidx[a] == e) {
            d_tok[p] = a >> 2;
            d_wt[p]  = d_topk_w[a];
            d_pos[a] = p;
            p++;
        }
    }
}

// ---------------- 3. Gather x rows -> fp16 ----------------
__global__ void gather_kernel(const float* __restrict__ x) {
    int p = blockIdx.x;
    int tok = d_tok[p];
    const float4* src = (const float4*)(x + (size_t)tok * H_);
    uint32_t* dst = (uint32_t*)(d_xs16 + (size_t)p * H_);
    for (int i = threadIdx.x; i < H_ / 4; i += 256) {
        float4 v = src[i];
        dst[2 * i]     = pack_f2h(v.x, v.y);
        dst[2 * i + 1] = pack_f2h(v.z, v.w);
    }
}

// ---------------- 4. Grouped GEMM (fp16 mma.sync) ----------------
// mode 0: Cf = A*B^T                      (gate -> d_g fp32)
// mode 1: Ch = h16(silu(G)*(A*B^T))       (up, fused SiLU -> d_h16)
// mode 2: Cf = wt[m] * A*B^T              (down -> d_obuf fp32)
#define ISSUE_STAGE(kt, st) do {                                                  \
    if ((kt) < NT) {                                                              \
        int k0 = (kt) * BK;                                                       \
        uint32_t sa = smbase + (st) * STAGE_BYTES;                                \
        uint32_t sbb = sa + A_BYTES;                                              \
        _Pragma("unroll")                                                         \
        for (int i = 0; i < 8; i++) {                                             \
            int r = lr + 32 * i;                                                  \
            uint32_t sw = (uint32_t)(r * 128 + ((lj ^ (r & 7)) << 4));            \
            int ra = base + m0 + r; if (ra > A_TOT - 1) ra = A_TOT - 1;           \
            const __half* srca = A + (size_t)ra * Kdim + k0 + lj * 8;             \
            int vs = (m0 + r < n_e) ? 16 : 0;                                     \
            asm volatile("cp.async.cg.shared.global [%0], [%1], 16, %2;"          \
                         :: "r"(sa + sw), "l"(srca), "r"(vs) : "memory");         \
        }                                                                         \
        _Pragma("unroll")                                                         \
        for (int i = 0; i < 4; i++) {                                             \
            int r = lr + 32 * i;                                                  \
            uint32_t sw = (uint32_t)(r * 128 + ((lj ^ (r & 7)) << 4));            \
            const __half* srcb = Bexp + (size_t)(n0 + r) * Kdim + k0 + lj * 8;    \
            asm volatile("cp.async.cg.shared.global [%0], [%1], 16;"              \
                         :: "r"(sbb + sw), "l"(srcb) : "memory");                 \
        }                                                                         \
    }                                                                             \
    asm volatile("cp.async.commit_group;" ::: "memory");                          \
} while (0)

__global__ __launch_bounds__(256)
void gemm_tc(const __half* __restrict__ A, const __half* __restrict__ Bw,
             float* __restrict__ Cf, __half* __restrict__ Ch,
             const float* __restrict__ G, int Kdim, int N, int mode) {
    int e = blockIdx.z;
    int base = d_off[e];
    int n_e  = d_off[e + 1] - base;
    int m0 = blockIdx.y * BM;
    if (m0 >= n_e) return;
    int n0 = blockIdx.x * BN;

    extern __shared__ char sm[];
    uint32_t smbase = smem_u32(sm);
    int tid = threadIdx.x;
    int wid = tid >> 5, lane = tid & 31;
    int q = lane >> 2, tig = lane & 3;
    int lr = tid >> 3, lj = tid & 7;          // cp.async: row-of-32, 16B chunk

    const __half* Bexp = Bw + (size_t)e * N * Kdim;
    int NT = Kdim / BK;

    ISSUE_STAGE(0, 0);
    ISSUE_STAGE(1, 1);

    int wm = (wid & 3) << 6;    // warp M band: 0/64/128/192
    int wn = (wid >> 2) << 6;   // warp N band: 0/64

    float acc[4][8][4];
#pragma unroll
    for (int mt = 0; mt < 4; mt++)
#pragma unroll
        for (int nt = 0; nt < 8; nt++)
#pragma unroll
            for (int r = 0; r < 4; r++) acc[mt][nt][r] = 0.f;

    // 32-bit word offsets into stage (A rows: 32 words/row; B after A)
    int rowA[4], rowB[8];
#pragma unroll
    for (int mt = 0; mt < 4; mt++) rowA[mt] = (wm + mt * 16 + q) * 32 + tig;
#pragma unroll
    for (int nt = 0; nt < 8; nt++) rowB[nt] = (A_BYTES / 4) + (wn + nt * 8 + q) * 32 + tig;

    for (int kt = 0; kt < NT; kt++) {
        asm volatile("cp.async.wait_group 1;" ::: "memory");
        __syncthreads();
        ISSUE_STAGE(kt + 2, (kt + 2) % STAGES);
        const uint32_t* Sw = (const uint32_t*)(sm + (kt % STAGES) * STAGE_BYTES);
#pragma unroll
        for (int kk = 0; kk < 4; kk++) {
            int x0 = (((2 * kk)     ^ q) << 2);
            int x1 = (((2 * kk + 1) ^ q) << 2);
            uint32_t a[4][4];
#pragma unroll
            for (int mt = 0; mt < 4; mt++) {
                a[mt][0] = Sw[rowA[mt] + x0];
                a[mt][1] = Sw[rowA[mt] + 256 + x0];
                a[mt][2] = Sw[rowA[mt] + x1];
                a[mt][3] = Sw[rowA[mt] + 256 + x1];
            }
            uint32_t b[8][2];
#pragma unroll
            for (int nt = 0; nt < 8; nt++) {
                b[nt][0] = Sw[rowB[nt] + x0];
                b[nt][1] = Sw[rowB[nt] + x1];
            }
#pragma unroll
            for (int mt = 0; mt < 4; mt++)
#pragma unroll
                for (int nt = 0; nt < 8; nt++)
                    MMA_F16(acc[mt][nt], a[mt], b[nt]);
        }
    }

    // epilogue
#pragma unroll
    for (int mt = 0; mt < 4; mt++) {
        int m  = m0 + wm + mt * 16 + q;
        int m8 = m + 8;
        float w0 = 1.f, w1 = 1.f;
        if (mode == 2) {
            w0 = (m  < n_e) ? d_wt[base + m]  : 0.f;
            w1 = (m8 < n_e) ? d_wt[base + m8] : 0.f;
        }
#pragma unroll
        for (int nt = 0; nt < 8; nt++) {
            int n = n0 + wn + nt * 8 + 2 * tig;
            if (m < n_e) {
                size_t o = (size_t)(base + m) * N + n;
                float vx = acc[mt][nt][0], vy = acc[mt][nt][1];
                if (mode == 1) {
                    float2 g = *(const float2*)&G[o];
                    vx = g.x * (1.f / (1.f + __expf(-g.x))) * vx;
                    vy = g.y * (1.f / (1.f + __expf(-g.y))) * vy;
                    *(uint32_t*)&Ch[o] = pack_f2h(vx, vy);
                } else {
                    *(float2*)&Cf[o] = make_float2(vx * w0, vy * w0);
                }
            }
            if (m8 < n_e) {
                size_t o = (size_t)(base + m8) * N + n;
                float vx = acc[mt][nt][2], vy = acc[mt][nt][3];
                if (mode == 1) {
                    float2 g = *(const float2*)&G[o];
                    vx = g.x * (1.f / (1.f + __expf(-g.x))) * vx;
                    vy = g.y * (1.f / (1.f + __expf(-g.y))) * vy;
                    *(uint32_t*)&Ch[o] = pack_f2h(vx, vy);
                } else {
                    *(float2*)&Cf[o] = make_float2(vx * w1, vy * w1);
                }
            }
        }
    }
}

// ---------------- 5. Combine ----------------
__global__ void combine_kernel(float* __restrict__ out) {
    int gid = blockIdx.x * blockDim.x + threadIdx.x;
    int t = gid / (H_ / 4);
    int h4 = (gid - t * (H_ / 4)) * 4;
    float4 s = make_float4(0.f, 0.f, 0.f, 0.f);
#pragma unroll
    for (int k = 0; k < K_; k++) {
        int p = d_pos[t * K_ + k];
        float4 v = *(const float4*)&d_obuf[(size_t)p * H_ + h4];
        s.x += v.x; s.y += v.y; s.z += v.z; s.w += v.w;
    }
    *(float4*)&out[(size_t)t * H_ + h4] = s;
}

// ---------------- Host ----------------
extern "C" void kernel_launch(void* const* d_in, const int* in_sizes, int n_in,
                              void* d_out, int out_size) {
    const float* x      = (const float*)d_in[0];
    const float* logits = (const float*)d_in[1];
    const float* gate_w = (const float*)d_in[2];
    const float* up_w   = (const float*)d_in[3];
    const float* down_w = (const float*)d_in[4];
    float* out = (float*)d_out;

    static int smem_set = 0;
    if (!smem_set) {
        cudaFuncSetAttribute(gemm_tc, cudaFuncAttributeMaxDynamicSharedMemorySize, GEMM_SMEM);
        smem_set = 1;
    }

    __half *xs_p, *gw_p, *uw_p, *dw_p, *h_p;
    float *g_p, *o_p;
    cudaGetSymbolAddress((void**)&xs_p, d_xs16);
    cudaGetSymbolAddress((void**)&gw_p, d_gw16);
    cudaGetSymbolAddress((void**)&uw_p, d_uw16);
    cudaGetSymbolAddress((void**)&dw_p, d_dw16);
    cudaGetSymbolAddress((void**)&g_p,  d_g);
    cudaGetSymbolAddress((void**)&h_p,  d_h16);
    cudaGetSymbolAddress((void**)&o_p,  d_obuf);

    size_t n8 = WELEM / 8;                 // 5,767,168
    int cb = (int)((n8 + 255) / 256);
    convert_kernel<<<cb, 256>>>((const float4*)gate_w, (uint4*)gw_p, n8);
    convert_kernel<<<cb, 256>>>((const float4*)up_w,   (uint4*)uw_p, n8);
    convert_kernel<<<cb, 256>>>((const float4*)down_w, (uint4*)dw_p, n8);

    router_kernel<<<T_ / 256, 256>>>(logits);
    sort_kernel<<<1, 256>>>();
    gather_kernel<<<A_TOT, 256>>>(x);

    dim3 g1(I_ / BN, T_ / BM, E_);   // 11 x 8 x 16
    gemm_tc<<<g1, 256, GEMM_SMEM>>>(xs_p, gw_p, g_p, nullptr, nullptr, H_, I_, 0);
    gemm_tc<<<g1, 256, GEMM_SMEM>>>(xs_p, uw_p, nullptr, h_p, g_p,     H_, I_, 1);

    dim3 g2(H_ / BN, T_ / BM, E_);   // 16 x 8 x 16
    gemm_tc<<<g2, 256, GEMM_SMEM>>>(h_p, dw_p, o_p, nullptr, nullptr, I_, H_, 2);

    combine_kernel<<<(T_ * H_ / 4) / 256, 256>>>(out);
}

// round 7
// speedup vs baseline: 1.6311x; 1.0855x over previous
#include <cuda_runtime.h>
#include <cuda_fp16.h>
#include <math.h>
#include <stdint.h>

// Problem constants
#define T_   2048
#define E_   16
#define H_   2048
#define I_   1408
#define K_   4
#define A_TOT (T_ * K_)   // 8192 assignments
#define WELEM ((size_t)E_ * I_ * H_)   // 46,137,344

// GEMM tiling (fp16 mma.sync m16n8k16 + ldmatrix), CTA 256x128, warp 64x64
#define BM 256
#define BN 128
#define BK 64                         // halves per k-tile (128 bytes per row)
#define STAGES 3
#define A_BYTES (BM * 128)            // 32768
#define B_BYTES (BN * 128)            // 16384
#define STAGE_BYTES (A_BYTES + B_BYTES)      // 49152
#define GEMM_SMEM (STAGES * STAGE_BYTES)     // 147456

// ---------------- Device scratch ----------------
__device__ int    d_topk_idx[A_TOT];
__device__ float  d_topk_w[A_TOT];
__device__ int    d_tok[A_TOT];
__device__ float  d_wt[A_TOT];
__device__ int    d_pos[A_TOT];
__device__ int    d_off[E_ + 1];
__device__ __half d_xs16[(size_t)A_TOT * H_];   // gathered x, fp16
__device__ __half d_cw16[2 * WELEM];            // interleaved gate/up weights fp16
__device__ __half d_dw16[WELEM];                // down_w fp16
__device__ __half d_h16[(size_t)A_TOT * I_];    // silu(g)*u fp16
__device__ float  d_obuf[(size_t)A_TOT * H_];   // weighted down outputs fp32

// ---------------- helpers ----------------
__device__ __forceinline__ uint32_t smem_u32(const void* p) {
    uint32_t a;
    asm("{ .reg .u64 t; cvta.to.shared.u64 t, %1; cvt.u32.u64 %0, t; }" : "=r"(a) : "l"(p));
    return a;
}
__device__ __forceinline__ uint32_t pack_f2h(float a, float b) {
    uint32_t r;
    asm("{ .reg .f16 lo, hi;\n\t"
        "cvt.rn.f16.f32 lo, %1;\n\t"
        "cvt.rn.f16.f32 hi, %2;\n\t"
        "mov.b32 %0, {lo, hi}; }"
        : "=r"(r) : "f"(a), "f"(b));
    return r;
}

#define MMA_F16(c, a, b) \
    asm volatile("mma.sync.aligned.m16n8k16.row.col.f32.f16.f16.f32 " \
        "{%0,%1,%2,%3}, {%4,%5,%6,%7}, {%8,%9}, {%0,%1,%2,%3};" \
        : "+f"((c)[0]), "+f"((c)[1]), "+f"((c)[2]), "+f"((c)[3]) \
        : "r"((a)[0]), "r"((a)[1]), "r"((a)[2]), "r"((a)[3]), "r"((b)[0]), "r"((b)[1]))

#define LDSM_X4(r0, r1, r2, r3, addr) \
    asm volatile("ldmatrix.sync.aligned.m8n8.x4.shared.b16 {%0,%1,%2,%3}, [%4];" \
        : "=r"(r0), "=r"(r1), "=r"(r2), "=r"(r3) : "r"(addr))

// ---------------- 0a. Interleaving weight convert (gate/up) ----------------
// src row (e*I + i) -> dst row (e*2I + 2i + off)
__global__ void convert_inter(const float4* __restrict__ src, int off) {
    size_t i = (size_t)blockIdx.x * blockDim.x + threadIdx.x;   // over WELEM/8
    if (i >= WELEM / 8) return;
    size_t elem = i * 8;
    int row = (int)(elem / H_);
    int col = (int)(elem % H_);
    int e = row / I_, ir = row - e * I_;
    size_t drow = (size_t)e * 2 * I_ + 2 * ir + off;
    float4 v0 = src[2 * i];
    float4 v1 = src[2 * i + 1];
    uint4 o;
    o.x = pack_f2h(v0.x, v0.y);
    o.y = pack_f2h(v0.z, v0.w);
    o.z = pack_f2h(v1.x, v1.y);
    o.w = pack_f2h(v1.z, v1.w);
    *(uint4*)&d_cw16[drow * H_ + col] = o;
}

// ---------------- 0b. Plain weight convert (down) ----------------
__global__ void convert_kernel(const float4* __restrict__ src, uint4* __restrict__ dst,
                               size_t n8) {
    size_t i = (size_t)blockIdx.x * blockDim.x + threadIdx.x;
    if (i >= n8) return;
    float4 v0 = src[2 * i];
    float4 v1 = src[2 * i + 1];
    uint4 o;
    o.x = pack_f2h(v0.x, v0.y);
    o.y = pack_f2h(v0.z, v0.w);
    o.z = pack_f2h(v1.x, v1.y);
    o.w = pack_f2h(v1.z, v1.w);
    dst[i] = o;
}

// ---------------- 1. Router ----------------
__global__ void router_kernel(const float* __restrict__ logits) {
    int t = blockIdx.x * blockDim.x + threadIdx.x;
    if (t >= T_) return;
    float l[E_];
#pragma unroll
    for (int e = 0; e < E_; e++) l[e] = logits[t * E_ + e];
    unsigned used = 0u;
    float val[K_]; int idx[K_];
#pragma unroll
    for (int k = 0; k < K_; k++) {
        float bv = -INFINITY; int bi = 0;
#pragma unroll
        for (int e = 0; e < E_; e++) {
            bool ok = !((used >> e) & 1u) && (l[e] > bv);
            bv = ok ? l[e] : bv;
            bi = ok ? e : bi;
        }
        used |= (1u << bi);
        val[k] = bv; idx[k] = bi;
    }
    float m = val[0], s = 0.f;
#pragma unroll
    for (int k = 0; k < K_; k++) { val[k] = __expf(val[k] - m); s += val[k]; }
    float inv = 1.f / s;
#pragma unroll
    for (int k = 0; k < K_; k++) {
        d_topk_idx[t * K_ + k] = idx[k];
        d_topk_w[t * K_ + k]   = val[k] * inv;
    }
}

// ---------------- 2. Deterministic counting sort ----------------
__global__ void sort_kernel() {
    __shared__ int sidx[A_TOT];
    __shared__ int scnt[256];
    __shared__ int sbase[256];
    int tid = threadIdx.x;
    for (int a = tid; a < A_TOT; a += 256) sidx[a] = d_topk_idx[a];
    __syncthreads();
    const int CH = A_TOT / 16;
    int e = tid >> 4, c = tid & 15, cn = 0;
    for (int a = c * CH; a < (c + 1) * CH; a++) cn += (sidx[a] == e);
    scnt[tid] = cn;
    __syncthreads();
    if (tid == 0) {
        int run = 0;
        for (int ee = 0; ee < E_; ee++) {
            d_off[ee] = run;
            for (int cc = 0; cc < 16; cc++) { sbase[ee * 16 + cc] = run; run += scnt[ee * 16 + cc]; }
        }
        d_off[E_] = run;
    }
    __syncthreads();
    int p = sbase[tid];
    for (int a = c * CH; a < (c + 1) * CH; a++) {
        if (sidx[a] == e) {
            d_tok[p] = a >> 2;
            d_wt[p]  = d_topk_w[a];
            d_pos[a] = p;
            p++;
        }
    }
}

// ---------------- 3. Gather x rows -> fp16 ----------------
__global__ void gather_kernel(const float* __restrict__ x) {
    int p = blockIdx.x;
    int tok = d_tok[p];
    const float4* src = (const float4*)(x + (size_t)tok * H_);
    uint32_t* dst = (uint32_t*)(d_xs16 + (size_t)p * H_);
    for (int i = threadIdx.x; i < H_ / 4; i += 256) {
        float4 v = src[i];
        dst[2 * i]     = pack_f2h(v.x, v.y);
        dst[2 * i + 1] = pack_f2h(v.z, v.w);
    }
}

// ---------------- 4. Grouped GEMM (fp16 mma.sync + ldmatrix) ----------------
// mode 1: interleaved gate/up B -> d_h16 = f16(silu(g)*u)   (Nb = 2*I_)
// mode 2: down B, weighted      -> d_obuf (fp32)            (Nb = H_)
#define ISSUE_STAGE(kt, st) do {                                                  \
    if ((kt) < NT) {                                                              \
        int k0 = (kt) * BK;                                                       \
        uint32_t sa = smbase + (st) * STAGE_BYTES;                                \
        uint32_t sbb = sa + A_BYTES;                                              \
        _Pragma("unroll")                                                         \
        for (int i = 0; i < 8; i++) {                                             \
            int r = lr + 32 * i;                                                  \
            uint32_t sw = (uint32_t)(r * 128 + ((lj ^ (r & 7)) << 4));            \
            int ra = base + m0 + r; if (ra > A_TOT - 1) ra = A_TOT - 1;           \
            const __half* srca = A + (size_t)ra * Kdim + k0 + lj * 8;             \
            int vs = (m0 + r < n_e) ? 16 : 0;                                     \
            asm volatile("cp.async.cg.shared.global [%0], [%1], 16, %2;"          \
                         :: "r"(sa + sw), "l"(srca), "r"(vs) : "memory");         \
        }                                                                         \
        _Pragma("unroll")                                                         \
        for (int i = 0; i < 4; i++) {                                             \
            int r = lr + 32 * i;                                                  \
            uint32_t sw = (uint32_t)(r * 128 + ((lj ^ (r & 7)) << 4));            \
            const __half* srcb = Bexp + (size_t)(n0 + r) * Kdim + k0 + lj * 8;    \
            asm volatile("cp.async.cg.shared.global [%0], [%1], 16;"              \
                         :: "r"(sbb + sw), "l"(srcb) : "memory");                 \
        }                                                                         \
    }                                                                             \
    asm volatile("cp.async.commit_group;" ::: "memory");                          \
} while (0)

__global__ __launch_bounds__(256)
void gemm_tc(const __half* __restrict__ A, const __half* __restrict__ Bw,
             int Kdim, int Nb, int mode) {
    int e = blockIdx.z;
    int base = d_off[e];
    int n_e  = d_off[e + 1] - base;
    int m0 = blockIdx.y * BM;
    if (m0 >= n_e) return;
    int n0 = blockIdx.x * BN;

    extern __shared__ char sm[];
    uint32_t smbase = smem_u32(sm);
    int tid = threadIdx.x;
    int wid = tid >> 5, lane = tid & 31;
    int q = lane >> 2, tig = lane & 3;
    int lr = tid >> 3, lj = tid & 7;          // cp.async: row-of-32, 16B chunk

    const __half* Bexp = Bw + (size_t)e * Nb * Kdim;
    int NT = Kdim / BK;

    ISSUE_STAGE(0, 0);
    ISSUE_STAGE(1, 1);

    int wm = (wid & 3) << 6;    // warp M band: 0/64/128/192
    int wn = (wid >> 2) << 6;   // warp N band: 0/64

    // ldmatrix per-thread geometry
    int c7 = lane & 7;
    int subA_m = (lane >> 3) & 1;    // sub&1: +8 rows
    int subA_k = (lane >> 4) & 1;    // sub>>1: k chunk +1
    int subB_k = (lane >> 3) & 1;
    int subB_n = (lane >> 4) & 1;
    uint32_t rowbaseA[4], rowbaseB[4];
#pragma unroll
    for (int mt = 0; mt < 4; mt++)
        rowbaseA[mt] = (uint32_t)((wm + mt * 16 + subA_m * 8 + c7) * 128);
#pragma unroll
    for (int p = 0; p < 4; p++)
        rowbaseB[p] = (uint32_t)(A_BYTES + (wn + p * 16 + subB_n * 8 + c7) * 128);

    float acc[4][8][4];
#pragma unroll
    for (int mt = 0; mt < 4; mt++)
#pragma unroll
        for (int nt = 0; nt < 8; nt++)
#pragma unroll
            for (int r = 0; r < 4; r++) acc[mt][nt][r] = 0.f;

    for (int kt = 0; kt < NT; kt++) {
        asm volatile("cp.async.wait_group 1;" ::: "memory");
        __syncthreads();
        ISSUE_STAGE(kt + 2, (kt + 2) % STAGES);
        uint32_t stg = smbase + (kt % STAGES) * STAGE_BYTES;
#pragma unroll
        for (int kk = 0; kk < 4; kk++) {
            uint32_t offA = (uint32_t)(((2 * kk + subA_k) ^ c7) << 4);
            uint32_t offB = (uint32_t)(((2 * kk + subB_k) ^ c7) << 4);
            uint32_t a[4][4];
#pragma unroll
            for (int mt = 0; mt < 4; mt++)
                LDSM_X4(a[mt][0], a[mt][1], a[mt][2], a[mt][3],
                        stg + rowbaseA[mt] + offA);
            uint32_t b[8][2];
#pragma unroll
            for (int p = 0; p < 4; p++)
                LDSM_X4(b[2 * p][0], b[2 * p][1], b[2 * p + 1][0], b[2 * p + 1][1],
                        stg + rowbaseB[p] + offB);
#pragma unroll
            for (int mt = 0; mt < 4; mt++)
#pragma unroll
                for (int nt = 0; nt < 8; nt++)
                    MMA_F16(acc[mt][nt], a[mt], b[nt]);
        }
    }

    // epilogue
#pragma unroll
    for (int mt = 0; mt < 4; mt++) {
        int m  = m0 + wm + mt * 16 + q;
        int m8 = m + 8;
        if (mode == 1) {
            // interleaved: acc[nt][0]=gate(col n), acc[nt][1]=up(col n+1); feature = n/2
#pragma unroll
            for (int nt = 0; nt < 8; nt++) {
                int f = (n0 + wn + nt * 8) / 2 + tig;
                if (m < n_e) {
                    float g = acc[mt][nt][0], u = acc[mt][nt][1];
                    float h = g * (1.f / (1.f + __expf(-g))) * u;
                    d_h16[(size_t)(base + m) * I_ + f] = __float2half_rn(h);
                }
                if (m8 < n_e) {
                    float g = acc[mt][nt][2], u = acc[mt][nt][3];
                    float h = g * (1.f / (1.f + __expf(-g))) * u;
                    d_h16[(size_t)(base + m8) * I_ + f] = __float2half_rn(h);
                }
            }
        } else {
            float w0 = (m  < n_e) ? d_wt[base + m]  : 0.f;
            float w1 = (m8 < n_e) ? d_wt[base + m8] : 0.f;
#pragma unroll
            for (int nt = 0; nt < 8; nt++) {
                int n = n0 + wn + nt * 8 + 2 * tig;
                if (m < n_e)
                    *(float2*)&d_obuf[(size_t)(base + m) * H_ + n] =
                        make_float2(acc[mt][nt][0] * w0, acc[mt][nt][1] * w0);
                if (m8 < n_e)
                    *(float2*)&d_obuf[(size_t)(base + m8) * H_ + n] =
                        make_float2(acc[mt][nt][2] * w1, acc[mt][nt][3] * w1);
            }
        }
    }
}

// ---------------- 5. Combine ----------------
__global__ void combine_kernel(float* __restrict__ out) {
    int gid = blockIdx.x * blockDim.x + threadIdx.x;
    int t = gid / (H_ / 4);
    int h4 = (gid - t * (H_ / 4)) * 4;
    float4 s = make_float4(0.f, 0.f, 0.f, 0.f);
#pragma unroll
    for (int k = 0; k < K_; k++) {
        int p = d_pos[t * K_ + k];
        float4 v = *(const float4*)&d_obuf[(size_t)p * H_ + h4];
        s.x += v.x; s.y += v.y; s.z += v.z; s.w += v.w;
    }
    *(float4*)&out[(size_t)t * H_ + h4] = s;
}

// ---------------- Host ----------------
extern "C" void kernel_launch(void* const* d_in, const int* in_sizes, int n_in,
                              void* d_out, int out_size) {
    const float* x      = (const float*)d_in[0];
    const float* logits = (const float*)d_in[1];
    const float* gate_w = (const float*)d_in[2];
    const float* up_w   = (const float*)d_in[3];
    const float* down_w = (const float*)d_in[4];
    float* out = (float*)d_out;

    static int smem_set = 0;
    if (!smem_set) {
        cudaFuncSetAttribute(gemm_tc, cudaFuncAttributeMaxDynamicSharedMemorySize, GEMM_SMEM);
        smem_set = 1;
    }

    __half *xs_p, *cw_p, *dw_p, *h_p;
    cudaGetSymbolAddress((void**)&xs_p, d_xs16);
    cudaGetSymbolAddress((void**)&cw_p, d_cw16);
    cudaGetSymbolAddress((void**)&dw_p, d_dw16);
    cudaGetSymbolAddress((void**)&h_p,  d_h16);

    size_t n8 = WELEM / 8;                 // 5,767,168
    int cb = (int)((n8 + 255) / 256);
    convert_inter<<<cb, 256>>>((const float4*)gate_w, 0);
    convert_inter<<<cb, 256>>>((const float4*)up_w,   1);
    convert_kernel<<<cb, 256>>>((const float4*)down_w, (uint4*)dw_p, n8);

    router_kernel<<<T_ / 256, 256>>>(logits);
    sort_kernel<<<1, 256>>>();
    gather_kernel<<<A_TOT, 256>>>(x);

    dim3 g1(2 * I_ / BN, 16, E_);   // 22 x 16 x 16 (y=16 for skew headroom)
    gemm_tc<<<g1, 256, GEMM_SMEM>>>(xs_p, cw_p, H_, 2 * I_, 1);

    dim3 g2(H_ / BN, 16, E_);       // 16 x 16 x 16
    gemm_tc<<<g2, 256, GEMM_SMEM>>>(h_p, dw_p, I_, H_, 2);

    combine_kernel<<<(T_ * H_ / 4) / 256, 256>>>(out);
}

// round 8
// speedup vs baseline: 1.9519x; 1.1967x over previous
#include <cuda_runtime.h>
#include <cuda_fp16.h>
#include <math.h>
#include <stdint.h>

// Problem constants
#define T_   2048
#define E_   16
#define H_   2048
#define I_   1408
#define K_   4
#define A_TOT (T_ * K_)   // 8192 assignments
#define WELEM ((size_t)E_ * I_ * H_)   // 46,137,344

// GEMM tiling: CTA 128x128, 4 warps (warp 64x64), fp16 m16n8k16 + ldmatrix
#define BM 128
#define BN 128
#define BK 64                         // halves per k-tile (128 bytes per row)
#define STAGES 3
#define NTHR 128
#define A_BYTES (BM * 128)            // 16384
#define B_BYTES (BN * 128)            // 16384
#define STAGE_BYTES (A_BYTES + B_BYTES)      // 32768
#define GEMM_SMEM (STAGES * STAGE_BYTES)     // 98304

// ---------------- Device scratch ----------------
__device__ int    d_topk_idx[A_TOT];
__device__ float  d_topk_w[A_TOT];
__device__ int    d_tok[A_TOT];
__device__ float  d_wt[A_TOT];
__device__ int    d_pos[A_TOT];
__device__ int    d_off[E_ + 1];
__device__ __half d_xs16[(size_t)A_TOT * H_];   // gathered x, fp16
__device__ __half d_cw16[2 * WELEM];            // interleaved gate/up weights fp16
__device__ __half d_dw16[WELEM];                // down_w fp16
__device__ __half d_h16[(size_t)A_TOT * I_];    // silu(g)*u fp16
__device__ float  d_obuf[(size_t)A_TOT * H_];   // weighted down outputs fp32

// ---------------- helpers ----------------
__device__ __forceinline__ uint32_t smem_u32(const void* p) {
    uint32_t a;
    asm("{ .reg .u64 t; cvta.to.shared.u64 t, %1; cvt.u32.u64 %0, t; }" : "=r"(a) : "l"(p));
    return a;
}
__device__ __forceinline__ uint32_t pack_f2h(float a, float b) {
    uint32_t r;
    asm("{ .reg .f16 lo, hi;\n\t"
        "cvt.rn.f16.f32 lo, %1;\n\t"
        "cvt.rn.f16.f32 hi, %2;\n\t"
        "mov.b32 %0, {lo, hi}; }"
        : "=r"(r) : "f"(a), "f"(b));
    return r;
}

#define MMA_F16(c, a, b) \
    asm volatile("mma.sync.aligned.m16n8k16.row.col.f32.f16.f16.f32 " \
        "{%0,%1,%2,%3}, {%4,%5,%6,%7}, {%8,%9}, {%0,%1,%2,%3};" \
        : "+f"((c)[0]), "+f"((c)[1]), "+f"((c)[2]), "+f"((c)[3]) \
        : "r"((a)[0]), "r"((a)[1]), "r"((a)[2]), "r"((a)[3]), "r"((b)[0]), "r"((b)[1]))

#define LDSM_X4(r0, r1, r2, r3, addr) \
    asm volatile("ldmatrix.sync.aligned.m8n8.x4.shared.b16 {%0,%1,%2,%3}, [%4];" \
        : "=r"(r0), "=r"(r1), "=r"(r2), "=r"(r3) : "r"(addr))

// ---------------- 0a. Interleaving weight convert (gate/up) ----------------
// src row (e*I + i) -> dst row (e*2I + 2i + off)
__global__ void convert_inter(const float4* __restrict__ src, int off) {
    size_t i = (size_t)blockIdx.x * blockDim.x + threadIdx.x;   // over WELEM/8
    if (i >= WELEM / 8) return;
    size_t elem = i * 8;
    int row = (int)(elem / H_);
    int col = (int)(elem % H_);
    int e = row / I_, ir = row - e * I_;
    size_t drow = (size_t)e * 2 * I_ + 2 * ir + off;
    float4 v0 = src[2 * i];
    float4 v1 = src[2 * i + 1];
    uint4 o;
    o.x = pack_f2h(v0.x, v0.y);
    o.y = pack_f2h(v0.z, v0.w);
    o.z = pack_f2h(v1.x, v1.y);
    o.w = pack_f2h(v1.z, v1.w);
    *(uint4*)&d_cw16[drow * H_ + col] = o;
}

// ---------------- 0b. Plain weight convert (down) ----------------
__global__ void convert_kernel(const float4* __restrict__ src, uint4* __restrict__ dst,
                               size_t n8) {
    size_t i = (size_t)blockIdx.x * blockDim.x + threadIdx.x;
    if (i >= n8) return;
    float4 v0 = src[2 * i];
    float4 v1 = src[2 * i + 1];
    uint4 o;
    o.x = pack_f2h(v0.x, v0.y);
    o.y = pack_f2h(v0.z, v0.w);
    o.z = pack_f2h(v1.x, v1.y);
    o.w = pack_f2h(v1.z, v1.w);
    dst[i] = o;
}

// ---------------- 1. Router ----------------
__global__ void router_kernel(const float* __restrict__ logits) {
    int t = blockIdx.x * blockDim.x + threadIdx.x;
    if (t >= T_) return;
    float l[E_];
#pragma unroll
    for (int e = 0; e < E_; e++) l[e] = logits[t * E_ + e];
    unsigned used = 0u;
    float val[K_]; int idx[K_];
#pragma unroll
    for (int k = 0; k < K_; k++) {
        float bv = -INFINITY; int bi = 0;
#pragma unroll
        for (int e = 0; e < E_; e++) {
            bool ok = !((used >> e) & 1u) && (l[e] > bv);
            bv = ok ? l[e] : bv;
            bi = ok ? e : bi;
        }
        used |= (1u << bi);
        val[k] = bv; idx[k] = bi;
    }
    float m = val[0], s = 0.f;
#pragma unroll
    for (int k = 0; k < K_; k++) { val[k] = __expf(val[k] - m); s += val[k]; }
    float inv = 1.f / s;
#pragma unroll
    for (int k = 0; k < K_; k++) {
        d_topk_idx[t * K_ + k] = idx[k];
        d_topk_w[t * K_ + k]   = val[k] * inv;
    }
}

// ---------------- 2. Deterministic counting sort ----------------
__global__ void sort_kernel() {
    __shared__ int sidx[A_TOT];
    __shared__ int scnt[256];
    __shared__ int sbase[256];
    int tid = threadIdx.x;
    for (int a = tid; a < A_TOT; a += 256) sidx[a] = d_topk_idx[a];
    __syncthreads();
    const int CH = A_TOT / 16;
    int e = tid >> 4, c = tid & 15, cn = 0;
    for (int a = c * CH; a < (c + 1) * CH; a++) cn += (sidx[a] == e);
    scnt[tid] = cn;
    __syncthreads();
    if (tid == 0) {
        int run = 0;
        for (int ee = 0; ee < E_; ee++) {
            d_off[ee] = run;
            for (int cc = 0; cc < 16; cc++) { sbase[ee * 16 + cc] = run; run += scnt[ee * 16 + cc]; }
        }
        d_off[E_] = run;
    }
    __syncthreads();
    int p = sbase[tid];
    for (int a = c * CH; a < (c + 1) * CH; a++) {
        if (sidx[a] == e) {
            d_tok[p] = a >> 2;
            d_wt[p]  = d_topk_w[a];
            d_pos[a] = p;
            p++;
        }
    }
}

// ---------------- 3. Gather x rows -> fp16 ----------------
__global__ void gather_kernel(const float* __restrict__ x) {
    int p = blockIdx.x;
    int tok = d_tok[p];
    const float4* src = (const float4*)(x + (size_t)tok * H_);
    uint32_t* dst = (uint32_t*)(d_xs16 + (size_t)p * H_);
    for (int i = threadIdx.x; i < H_ / 4; i += 256) {
        float4 v = src[i];
        dst[2 * i]     = pack_f2h(v.x, v.y);
        dst[2 * i + 1] = pack_f2h(v.z, v.w);
    }
}

// ---------------- 4. Grouped GEMM (fp16 mma.sync + ldmatrix) ----------------
// mode 1: interleaved gate/up B -> d_h16 = f16(silu(g)*u)   (Nb = 2*I_)
// mode 2: down B, weighted      -> d_obuf (fp32)            (Nb = H_)
// 128 threads: lj = tid&7 (16B chunk), lr = tid>>3 (0..15), rows r = lr + 16*i
#define ISSUE_STAGE(kt, st) do {                                                  \
    if ((kt) < NT) {                                                              \
        int k0 = (kt) * BK;                                                       \
        uint32_t sa = smbase + (st) * STAGE_BYTES;                                \
        uint32_t sbb = sa + A_BYTES;                                              \
        _Pragma("unroll")                                                         \
        for (int i = 0; i < 8; i++) {                                             \
            int r = lr + 16 * i;                                                  \
            uint32_t sw = (uint32_t)(r * 128 + ((lj ^ (r & 7)) << 4));            \
            int ra = base + m0 + r; if (ra > A_TOT - 1) ra = A_TOT - 1;           \
            const __half* srca = A + (size_t)ra * Kdim + k0 + lj * 8;             \
            int vs = (m0 + r < n_e) ? 16 : 0;                                     \
            asm volatile("cp.async.cg.shared.global [%0], [%1], 16, %2;"          \
                         :: "r"(sa + sw), "l"(srca), "r"(vs) : "memory");         \
        }                                                                         \
        _Pragma("unroll")                                                         \
        for (int i = 0; i < 8; i++) {                                             \
            int r = lr + 16 * i;                                                  \
            uint32_t sw = (uint32_t)(r * 128 + ((lj ^ (r & 7)) << 4));            \
            const __half* srcb = Bexp + (size_t)(n0 + r) * Kdim + k0 + lj * 8;    \
            asm volatile("cp.async.cg.shared.global [%0], [%1], 16;"              \
                         :: "r"(sbb + sw), "l"(srcb) : "memory");                 \
        }                                                                         \
    }                                                                             \
    asm volatile("cp.async.commit_group;" ::: "memory");                          \
} while (0)

__global__ __launch_bounds__(NTHR)
void gemm_tc(const __half* __restrict__ A, const __half* __restrict__ Bw,
             int Kdim, int Nb, int mode) {
    int e = blockIdx.z;
    int base = d_off[e];
    int n_e  = d_off[e + 1] - base;
    int m0 = blockIdx.y * BM;
    if (m0 >= n_e) return;
    int n0 = blockIdx.x * BN;

    extern __shared__ char sm[];
    uint32_t smbase = smem_u32(sm);
    int tid = threadIdx.x;
    int wid = tid >> 5, lane = tid & 31;
    int q = lane >> 2, tig = lane & 3;
    int lr = tid >> 3, lj = tid & 7;

    const __half* Bexp = Bw + (size_t)e * Nb * Kdim;
    int NT = Kdim / BK;

    ISSUE_STAGE(0, 0);
    ISSUE_STAGE(1, 1);

    int wm = (wid & 1) << 6;    // warp M band: 0/64
    int wn = (wid >> 1) << 6;   // warp N band: 0/64

    // ldmatrix per-thread geometry
    int c7 = lane & 7;
    int subA_m = (lane >> 3) & 1;
    int subA_k = (lane >> 4) & 1;
    int subB_k = (lane >> 3) & 1;
    int subB_n = (lane >> 4) & 1;
    uint32_t rowbaseA[4], rowbaseB[4];
#pragma unroll
    for (int mt = 0; mt < 4; mt++)
        rowbaseA[mt] = (uint32_t)((wm + mt * 16 + subA_m * 8 + c7) * 128);
#pragma unroll
    for (int p = 0; p < 4; p++)
        rowbaseB[p] = (uint32_t)(A_BYTES + (wn + p * 16 + subB_n * 8 + c7) * 128);

    float acc[4][8][4];
#pragma unroll
    for (int mt = 0; mt < 4; mt++)
#pragma unroll
        for (int nt = 0; nt < 8; nt++)
#pragma unroll
            for (int r = 0; r < 4; r++) acc[mt][nt][r] = 0.f;

    for (int kt = 0; kt < NT; kt++) {
        asm volatile("cp.async.wait_group 1;" ::: "memory");
        __syncthreads();
        ISSUE_STAGE(kt + 2, (kt + 2) % STAGES);
        uint32_t stg = smbase + (kt % STAGES) * STAGE_BYTES;
#pragma unroll
        for (int kk = 0; kk < 4; kk++) {
            uint32_t offA = (uint32_t)(((2 * kk + subA_k) ^ c7) << 4);
            uint32_t offB = (uint32_t)(((2 * kk + subB_k) ^ c7) << 4);
            uint32_t a[4][4];
#pragma unroll
            for (int mt = 0; mt < 4; mt++)
                LDSM_X4(a[mt][0], a[mt][1], a[mt][2], a[mt][3],
                        stg + rowbaseA[mt] + offA);
            uint32_t b[8][2];
#pragma unroll
            for (int p = 0; p < 4; p++)
                LDSM_X4(b[2 * p][0], b[2 * p][1], b[2 * p + 1][0], b[2 * p + 1][1],
                        stg + rowbaseB[p] + offB);
#pragma unroll
            for (int mt = 0; mt < 4; mt++)
#pragma unroll
                for (int nt = 0; nt < 8; nt++)
                    MMA_F16(acc[mt][nt], a[mt], b[nt]);
        }
    }

    // epilogue
#pragma unroll
    for (int mt = 0; mt < 4; mt++) {
        int m  = m0 + wm + mt * 16 + q;
        int m8 = m + 8;
        if (mode == 1) {
#pragma unroll
            for (int nt = 0; nt < 8; nt++) {
                int f = (n0 + wn + nt * 8) / 2 + tig;
                if (m < n_e) {
                    float g = acc[mt][nt][0], u = acc[mt][nt][1];
                    float h = g * (1.f / (1.f + __expf(-g))) * u;
                    d_h16[(size_t)(base + m) * I_ + f] = __float2half_rn(h);
                }
                if (m8 < n_e) {
                    float g = acc[mt][nt][2], u = acc[mt][nt][3];
                    float h = g * (1.f / (1.f + __expf(-g))) * u;
                    d_h16[(size_t)(base + m8) * I_ + f] = __float2half_rn(h);
                }
            }
        } else {
            float w0 = (m  < n_e) ? d_wt[base + m]  : 0.f;
            float w1 = (m8 < n_e) ? d_wt[base + m8] : 0.f;
#pragma unroll
            for (int nt = 0; nt < 8; nt++) {
                int n = n0 + wn + nt * 8 + 2 * tig;
                if (m < n_e)
                    *(float2*)&d_obuf[(size_t)(base + m) * H_ + n] =
                        make_float2(acc[mt][nt][0] * w0, acc[mt][nt][1] * w0);
                if (m8 < n_e)
                    *(float2*)&d_obuf[(size_t)(base + m8) * H_ + n] =
                        make_float2(acc[mt][nt][2] * w1, acc[mt][nt][3] * w1);
            }
        }
    }
}

// ---------------- 5. Combine ----------------
__global__ void combine_kernel(float* __restrict__ out) {
    int gid = blockIdx.x * blockDim.x + threadIdx.x;
    int t = gid / (H_ / 4);
    int h4 = (gid - t * (H_ / 4)) * 4;
    float4 s = make_float4(0.f, 0.f, 0.f, 0.f);
#pragma unroll
    for (int k = 0; k < K_; k++) {
        int p = d_pos[t * K_ + k];
        float4 v = *(const float4*)&d_obuf[(size_t)p * H_ + h4];
        s.x += v.x; s.y += v.y; s.z += v.z; s.w += v.w;
    }
    *(float4*)&out[(size_t)t * H_ + h4] = s;
}

// ---------------- Host ----------------
extern "C" void kernel_launch(void* const* d_in, const int* in_sizes, int n_in,
                              void* d_out, int out_size) {
    const float* x      = (const float*)d_in[0];
    const float* logits = (const float*)d_in[1];
    const float* gate_w = (const float*)d_in[2];
    const float* up_w   = (const float*)d_in[3];
    const float* down_w = (const float*)d_in[4];
    float* out = (float*)d_out;

    static int smem_set = 0;
    if (!smem_set) {
        cudaFuncSetAttribute(gemm_tc, cudaFuncAttributeMaxDynamicSharedMemorySize, GEMM_SMEM);
        smem_set = 1;
    }

    __half *xs_p, *cw_p, *dw_p, *h_p;
    cudaGetSymbolAddress((void**)&xs_p, d_xs16);
    cudaGetSymbolAddress((void**)&cw_p, d_cw16);
    cudaGetSymbolAddress((void**)&dw_p, d_dw16);
    cudaGetSymbolAddress((void**)&h_p,  d_h16);

    size_t n8 = WELEM / 8;                 // 5,767,168
    int cb = (int)((n8 + 255) / 256);
    convert_inter<<<cb, 256>>>((const float4*)gate_w, 0);
    convert_inter<<<cb, 256>>>((const float4*)up_w,   1);
    convert_kernel<<<cb, 256>>>((const float4*)down_w, (uint4*)dw_p, n8);

    router_kernel<<<T_ / 256, 256>>>(logits);
    sort_kernel<<<1, 256>>>();
    gather_kernel<<<A_TOT, 256>>>(x);

    dim3 g1(2 * I_ / BN, 32, E_);   // 22 x 32 x 16 (4096-row headroom per expert)
    gemm_tc<<<g1, NTHR, GEMM_SMEM>>>(xs_p, cw_p, H_, 2 * I_, 1);

    dim3 g2(H_ / BN, 32, E_);       // 16 x 32 x 16
    gemm_tc<<<g2, NTHR, GEMM_SMEM>>>(h_p, dw_p, I_, H_, 2);

    combine_kernel<<<(T_ * H_ / 4) / 256, 256>>>(out);
}

// round 9
// speedup vs baseline: 2.1155x; 1.0838x over previous
#include <cuda_runtime.h>
#include <cuda_fp16.h>
#include <math.h>
#include <stdint.h>

// Problem constants
#define T_   2048
#define E_   16
#define H_   2048
#define I_   1408
#define K_   4
#define A_TOT (T_ * K_)   // 8192 assignments

// GEMM tiling: CTA 128x128, 4 warps (warp 64x64), fp16 m16n8k16 + ldmatrix
// A: fp16 cp.async 3-stage; B: fp32 LDG -> reg -> cvt -> fp16 smem double-buffer
#define BM 128
#define BN 128
#define BK 64                          // K elements per tile
#define NTHR 128
#define A_STAGE 16384                  // 128 rows x 128 B
#define A3 (3 * A_STAGE)               // 49152
#define BBUF 16384
#define GEMM_SMEM (A3 + 2 * BBUF)      // 81920

// ---------------- Device scratch ----------------
__device__ int    d_topk_idx[A_TOT];
__device__ float  d_topk_w[A_TOT];
__device__ int    d_tok[A_TOT];
__device__ float  d_wt[A_TOT];
__device__ int    d_pos[A_TOT];
__device__ int    d_off[E_ + 1];
__device__ __half d_xs16[(size_t)A_TOT * H_];   // gathered x, fp16
__device__ __half d_h16[(size_t)A_TOT * I_];    // silu(g)*u fp16
__device__ float  d_obuf[(size_t)A_TOT * H_];   // weighted down outputs fp32

// ---------------- helpers ----------------
__device__ __forceinline__ uint32_t smem_u32(const void* p) {
    uint32_t a;
    asm("{ .reg .u64 t; cvta.to.shared.u64 t, %1; cvt.u32.u64 %0, t; }" : "=r"(a) : "l"(p));
    return a;
}
__device__ __forceinline__ uint32_t pack_f2h(float a, float b) {
    uint32_t r;
    asm("{ .reg .f16 lo, hi;\n\t"
        "cvt.rn.f16.f32 lo, %1;\n\t"
        "cvt.rn.f16.f32 hi, %2;\n\t"
        "mov.b32 %0, {lo, hi}; }"
        : "=r"(r) : "f"(a), "f"(b));
    return r;
}

#define MMA_F16(c, a, b) \
    asm volatile("mma.sync.aligned.m16n8k16.row.col.f32.f16.f16.f32 " \
        "{%0,%1,%2,%3}, {%4,%5,%6,%7}, {%8,%9}, {%0,%1,%2,%3};" \
        : "+f"((c)[0]), "+f"((c)[1]), "+f"((c)[2]), "+f"((c)[3]) \
        : "r"((a)[0]), "r"((a)[1]), "r"((a)[2]), "r"((a)[3]), "r"((b)[0]), "r"((b)[1]))

#define LDSM_X4(r0, r1, r2, r3, addr) \
    asm volatile("ldmatrix.sync.aligned.m8n8.x4.shared.b16 {%0,%1,%2,%3}, [%4];" \
        : "=r"(r0), "=r"(r1), "=r"(r2), "=r"(r3) : "r"(addr))

// ---------------- 1. Router ----------------
__global__ void router_kernel(const float* __restrict__ logits) {
    int t = blockIdx.x * blockDim.x + threadIdx.x;
    if (t >= T_) return;
    float l[E_];
#pragma unroll
    for (int e = 0; e < E_; e++) l[e] = logits[t * E_ + e];
    unsigned used = 0u;
    float val[K_]; int idx[K_];
#pragma unroll
    for (int k = 0; k < K_; k++) {
        float bv = -INFINITY; int bi = 0;
#pragma unroll
        for (int e = 0; e < E_; e++) {
            bool ok = !((used >> e) & 1u) && (l[e] > bv);
            bv = ok ? l[e] : bv;
            bi = ok ? e : bi;
        }
        used |= (1u << bi);
        val[k] = bv; idx[k] = bi;
    }
    float m = val[0], s = 0.f;
#pragma unroll
    for (int k = 0; k < K_; k++) { val[k] = __expf(val[k] - m); s += val[k]; }
    float inv = 1.f / s;
#pragma unroll
    for (int k = 0; k < K_; k++) {
        d_topk_idx[t * K_ + k] = idx[k];
        d_topk_w[t * K_ + k]   = val[k] * inv;
    }
}

// ---------------- 2. Deterministic counting sort ----------------
__global__ void sort_kernel() {
    __shared__ int sidx[A_TOT];
    __shared__ int scnt[256];
    __shared__ int sbase[256];
    int tid = threadIdx.x;
    for (int a = tid; a < A_TOT; a += 256) sidx[a] = d_topk_idx[a];
    __syncthreads();
    const int CH = A_TOT / 16;
    int e = tid >> 4, c = tid & 15, cn = 0;
    for (int a = c * CH; a < (c + 1) * CH; a++) cn += (sidx[a] == e);
    scnt[tid] = cn;
    __syncthreads();
    if (tid == 0) {
        int run = 0;
        for (int ee = 0; ee < E_; ee++) {
            d_off[ee] = run;
            for (int cc = 0; cc < 16; cc++) { sbase[ee * 16 + cc] = run; run += scnt[ee * 16 + cc]; }
        }
        d_off[E_] = run;
    }
    __syncthreads();
    int p = sbase[tid];
    for (int a = c * CH; a < (c + 1) * CH; a++) {
        if (sidx[a] == e) {
            d_tok[p] = a >> 2;
            d_wt[p]  = d_topk_w[a];
            d_pos[a] = p;
            p++;
        }
    }
}

// ---------------- 3. Gather x rows -> fp16 ----------------
__global__ void gather_kernel(const float* __restrict__ x) {
    int p = blockIdx.x;
    int tok = d_tok[p];
    const float4* src = (const float4*)(x + (size_t)tok * H_);
    uint32_t* dst = (uint32_t*)(d_xs16 + (size_t)p * H_);
    for (int i = threadIdx.x; i < H_ / 4; i += 256) {
        float4 v = src[i];
        dst[2 * i]     = pack_f2h(v.x, v.y);
        dst[2 * i + 1] = pack_f2h(v.z, v.w);
    }
}

// ---------------- 4. Grouped GEMM (fp16 mma + in-flight fp32->fp16 B convert) ----------------
// mode 1: B rows interleave gate(B0)/up(B1) features -> d_h16 = f16(silu(g)*u)
// mode 2: B = down(B0) -> d_obuf = wt * (A*B^T)  (fp32)
#define ISSUE_A(kt, st) do {                                                      \
    if ((kt) < NT) {                                                              \
        int k0 = (kt) * BK;                                                       \
        uint32_t sa = smbase + (st) * A_STAGE;                                    \
        _Pragma("unroll")                                                         \
        for (int i = 0; i < 8; i++) {                                             \
            int r = rr + 16 * i;                                                  \
            uint32_t sw = (uint32_t)(r * 128 + ((jc ^ (r & 7)) << 4));            \
            int ra = base + m0 + r; if (ra > A_TOT - 1) ra = A_TOT - 1;           \
            const __half* srca = A + (size_t)ra * Kdim + k0 + jc * 8;             \
            int vs = (m0 + r < n_e) ? 16 : 0;                                     \
            asm volatile("cp.async.cg.shared.global [%0], [%1], 16, %2;"          \
                         :: "r"(sa + sw), "l"(srca), "r"(vs) : "memory");         \
        }                                                                         \
    }                                                                             \
    asm volatile("cp.async.commit_group;" ::: "memory");                          \
} while (0)

#define LDG_B(kt) do {                                                            \
    int k0 = (kt) * BK;                                                           \
    _Pragma("unroll")                                                             \
    for (int i = 0; i < 8; i++) {                                                 \
        br[2 * i]     = *(const float4*)(bptr[i] + k0);                           \
        br[2 * i + 1] = *(const float4*)(bptr[i] + k0 + 4);                       \
    }                                                                             \
} while (0)

#define CVT_STS_B(buf) do {                                                       \
    uint32_t bs = smbase + A3 + (uint32_t)(buf) * BBUF;                           \
    _Pragma("unroll")                                                             \
    for (int i = 0; i < 8; i++) {                                                 \
        uint4 o;                                                                  \
        o.x = pack_f2h(br[2 * i].x,     br[2 * i].y);                             \
        o.y = pack_f2h(br[2 * i].z,     br[2 * i].w);                             \
        o.z = pack_f2h(br[2 * i + 1].x, br[2 * i + 1].y);                         \
        o.w = pack_f2h(br[2 * i + 1].z, br[2 * i + 1].w);                         \
        asm volatile("st.shared.v4.b32 [%0], {%1,%2,%3,%4};"                      \
                     :: "r"(bs + rowoff[i]), "r"(o.x), "r"(o.y), "r"(o.z),        \
                        "r"(o.w) : "memory");                                     \
    }                                                                             \
} while (0)

__global__ __launch_bounds__(NTHR, 2)
void gemm_tc(const __half* __restrict__ A, const float* __restrict__ B0,
             const float* __restrict__ B1, int Kdim, int mode) {
    int e = blockIdx.z;
    int base = d_off[e];
    int n_e  = d_off[e + 1] - base;
    int m0 = blockIdx.y * BM;
    if (m0 >= n_e) return;
    int n0 = blockIdx.x * BN;

    extern __shared__ char sm[];
    uint32_t smbase = smem_u32(sm);
    int tid = threadIdx.x;
    int wid = tid >> 5, lane = tid & 31;
    int q = lane >> 2, tig = lane & 3;
    int rr = tid >> 3, jc = tid & 7;     // loader: base row, 8-float chunk

    int NT = Kdim / BK;

    // B row source pointers + smem store offsets (8 rows per thread)
    const float* bptr[8];
    uint32_t rowoff[8];
#pragma unroll
    for (int i = 0; i < 8; i++) {
        int r = rr + 16 * i;
        rowoff[i] = (uint32_t)(r * 128 + ((jc ^ (r & 7)) << 4));
        if (mode == 1) {
            int f = (n0 >> 1) + (r >> 1);
            const float* srcw = (r & 1) ? B1 : B0;
            bptr[i] = srcw + ((size_t)e * I_ + f) * Kdim + jc * 8;
        } else {
            bptr[i] = B0 + ((size_t)e * H_ + n0 + r) * Kdim + jc * 8;
        }
    }

    float4 br[16];

    // prologue
    ISSUE_A(0, 0);
    ISSUE_A(1, 1);
    LDG_B(0);
    CVT_STS_B(0);
    __syncthreads();

    int wm = (wid & 1) << 6;    // warp M band: 0/64
    int wn = (wid >> 1) << 6;   // warp N band: 0/64

    // ldmatrix per-thread geometry
    int c7 = lane & 7;
    int subA_m = (lane >> 3) & 1;
    int subA_k = (lane >> 4) & 1;
    int subB_k = (lane >> 3) & 1;
    int subB_n = (lane >> 4) & 1;
    uint32_t rowbaseA[4], rowbaseB[4];
#pragma unroll
    for (int mt = 0; mt < 4; mt++)
        rowbaseA[mt] = (uint32_t)((wm + mt * 16 + subA_m * 8 + c7) * 128);
#pragma unroll
    for (int p = 0; p < 4; p++)
        rowbaseB[p] = (uint32_t)((wn + p * 16 + subB_n * 8 + c7) * 128);

    float acc[4][8][4];
#pragma unroll
    for (int mt = 0; mt < 4; mt++)
#pragma unroll
        for (int nt = 0; nt < 8; nt++)
#pragma unroll
            for (int r = 0; r < 4; r++) acc[mt][nt][r] = 0.f;

    for (int kt = 0; kt < NT; kt++) {
        if (kt + 1 < NT) LDG_B(kt + 1);
        ISSUE_A(kt + 2, (kt + 2) % 3);
        asm volatile("cp.async.wait_group 1;" ::: "memory");

        uint32_t stgA = smbase + (kt % 3) * A_STAGE;
        uint32_t stgB = smbase + A3 + (uint32_t)(kt & 1) * BBUF;
#pragma unroll
        for (int kk = 0; kk < 4; kk++) {
            uint32_t offA = (uint32_t)(((2 * kk + subA_k) ^ c7) << 4);
            uint32_t offB = (uint32_t)(((2 * kk + subB_k) ^ c7) << 4);
            uint32_t a[4][4];
#pragma unroll
            for (int mt = 0; mt < 4; mt++)
                LDSM_X4(a[mt][0], a[mt][1], a[mt][2], a[mt][3],
                        stgA + rowbaseA[mt] + offA);
            uint32_t b[8][2];
#pragma unroll
            for (int p = 0; p < 4; p++)
                LDSM_X4(b[2 * p][0], b[2 * p][1], b[2 * p + 1][0], b[2 * p + 1][1],
                        stgB + rowbaseB[p] + offB);
#pragma unroll
            for (int mt = 0; mt < 4; mt++)
#pragma unroll
                for (int nt = 0; nt < 8; nt++)
                    MMA_F16(acc[mt][nt], a[mt], b[nt]);
        }
        if (kt + 1 < NT) CVT_STS_B((kt + 1) & 1);
        __syncthreads();
    }

    // epilogue
#pragma unroll
    for (int mt = 0; mt < 4; mt++) {
        int m  = m0 + wm + mt * 16 + q;
        int m8 = m + 8;
        if (mode == 1) {
#pragma unroll
            for (int nt = 0; nt < 8; nt++) {
                int f = (n0 + wn + nt * 8) / 2 + tig;
                if (m < n_e) {
                    float g = acc[mt][nt][0], u = acc[mt][nt][1];
                    float h = g * (1.f / (1.f + __expf(-g))) * u;
                    d_h16[(size_t)(base + m) * I_ + f] = __float2half_rn(h);
                }
                if (m8 < n_e) {
                    float g = acc[mt][nt][2], u = acc[mt][nt][3];
                    float h = g * (1.f / (1.f + __expf(-g))) * u;
                    d_h16[(size_t)(base + m8) * I_ + f] = __float2half_rn(h);
                }
            }
        } else {
            float w0 = (m  < n_e) ? d_wt[base + m]  : 0.f;
            float w1 = (m8 < n_e) ? d_wt[base + m8] : 0.f;
#pragma unroll
            for (int nt = 0; nt < 8; nt++) {
                int n = n0 + wn + nt * 8 + 2 * tig;
                if (m < n_e)
                    *(float2*)&d_obuf[(size_t)(base + m) * H_ + n] =
                        make_float2(acc[mt][nt][0] * w0, acc[mt][nt][1] * w0);
                if (m8 < n_e)
                    *(float2*)&d_obuf[(size_t)(base + m8) * H_ + n] =
                        make_float2(acc[mt][nt][2] * w1, acc[mt][nt][3] * w1);
            }
        }
    }
}

// ---------------- 5. Combine ----------------
__global__ void combine_kernel(float* __restrict__ out) {
    int gid = blockIdx.x * blockDim.x + threadIdx.x;
    int t = gid / (H_ / 4);
    int h4 = (gid - t * (H_ / 4)) * 4;
    float4 s = make_float4(0.f, 0.f, 0.f, 0.f);
#pragma unroll
    for (int k = 0; k < K_; k++) {
        int p = d_pos[t * K_ + k];
        float4 v = *(const float4*)&d_obuf[(size_t)p * H_ + h4];
        s.x += v.x; s.y += v.y; s.z += v.z; s.w += v.w;
    }
    *(float4*)&out[(size_t)t * H_ + h4] = s;
}

// ---------------- Host ----------------
extern "C" void kernel_launch(void* const* d_in, const int* in_sizes, int n_in,
                              void* d_out, int out_size) {
    const float* x      = (const float*)d_in[0];
    const float* logits = (const float*)d_in[1];
    const float* gate_w = (const float*)d_in[2];
    const float* up_w   = (const float*)d_in[3];
    const float* down_w = (const float*)d_in[4];
    float* out = (float*)d_out;

    static int smem_set = 0;
    if (!smem_set) {
        cudaFuncSetAttribute(gemm_tc, cudaFuncAttributeMaxDynamicSharedMemorySize, GEMM_SMEM);
        smem_set = 1;
    }

    __half *xs_p, *h_p;
    cudaGetSymbolAddress((void**)&xs_p, d_xs16);
    cudaGetSymbolAddress((void**)&h_p,  d_h16);

    router_kernel<<<T_ / 256, 256>>>(logits);
    sort_kernel<<<1, 256>>>();
    gather_kernel<<<A_TOT, 256>>>(x);

    dim3 g1(2 * I_ / BN, 8, E_);   // 22 x 8 x 16
    gemm_tc<<<g1, NTHR, GEMM_SMEM>>>(xs_p, gate_w, up_w, H_, 1);

    dim3 g2(H_ / BN, 8, E_);       // 16 x 8 x 16
    gemm_tc<<<g2, NTHR, GEMM_SMEM>>>(h_p, down_w, nullptr, I_, 2);

    combine_kernel<<<(T_ * H_ / 4) / 256, 256>>>(out);
}